// round 6
// baseline (speedup 1.0000x reference)
#include <cuda_runtime.h>
#include <cstdint>

#define BDIM 32
#define PDIM 1024
#define VDIM 100
#define EDIM 512
#define HDIM 512
#define EPSV 1e-5f
#define MAXF 9216
#define PPAD (PDIM + 2)

// GEMM tiling: CTA 128x256, shared-B across taps, 2-stage cp.async pipeline
#define TM 128
#define TN 256
#define TK 32
#define NCHUNK (HDIM / TK)                 // 16
#define A_TAP_BYTES (TM * TK * 4)          // 16384 per tap
#define A_BYTES (3 * A_TAP_BYTES)          // 49152
#define B_ROWS_PAD 264                     // 256 + 2 halo, padded
#define B_BYTES (B_ROWS_PAD * 128)         // 33792
#define STAGE_BYTES (A_BYTES + B_BYTES)    // 82944
#define GEMM_SMEM (2 * STAGE_BYTES)        // 165888

// ---------------- scratch (static device globals) ----------------
__device__ float g_W1t[3 * EDIM * HDIM];            // [k][e][h]
__device__ float g_Atab[3 * VDIM * HDIM];           // [k][v][h]
__device__ float g_c1[HDIM];
__device__ float g_c2[HDIM];
__device__ float g_W2k[3 * HDIM * HDIM];            // [tap][h][h'] tf32-rounded, K-major
__device__ float g_y1t[(size_t)BDIM * PPAD * HDIM]; // [b][p+1][h'] tf32-rounded, halo rows zero
__device__ float g_y2[(size_t)BDIM * HDIM * PDIM];  // [b][h][p]
__device__ int   g_fidx[BDIM * MAXF];

// ---------------- PTX helpers (base ISA only) ----------------
__device__ __forceinline__ uint32_t smem_u32(const void* p) {
    uint32_t a;
    asm("{ .reg .u64 t; cvta.to.shared.u64 t, %1; cvt.u32.u64 %0, t; }" : "=r"(a) : "l"(p));
    return a;
}
__device__ __forceinline__ uint32_t f2tf32(float v) {
    uint32_t t;
    asm("cvt.rna.tf32.f32 %0, %1;" : "=r"(t) : "f"(v));
    return t;
}
__device__ __forceinline__ void cp_async16(uint32_t s, const void* g) {
    asm volatile("cp.async.cg.shared.global [%0], [%1], 16;" :: "r"(s), "l"(g) : "memory");
}
#define CP_COMMIT() asm volatile("cp.async.commit_group;" ::: "memory")
#define CP_WAIT1()  asm volatile("cp.async.wait_group 1;" ::: "memory")

#define LDSM_X4(r0, r1, r2, r3, addr)                                        \
    asm volatile("ldmatrix.sync.aligned.m8n8.x4.shared.b16 {%0,%1,%2,%3}, [%4];" \
        : "=r"(r0), "=r"(r1), "=r"(r2), "=r"(r3) : "r"(addr))

__device__ __forceinline__ void mma1688(float* d, uint32_t a0, uint32_t a1,
                                        uint32_t a2, uint32_t a3,
                                        uint32_t b0, uint32_t b1) {
    asm volatile(
        "mma.sync.aligned.m16n8k8.row.col.f32.tf32.tf32.f32 "
        "{%0,%1,%2,%3}, {%4,%5,%6,%7}, {%8,%9}, {%0,%1,%2,%3};"
        : "+f"(d[0]), "+f"(d[1]), "+f"(d[2]), "+f"(d[3])
        : "r"(a0), "r"(a1), "r"(a2), "r"(a3), "r"(b0), "r"(b1));
}

__device__ __forceinline__ uint32_t sw128(uint32_t off) { return off ^ ((off >> 3) & 0x70); }

// ---------------- launch 0: fold-BN vectors + W1 transpose + y1t halo zero ----------------
__global__ void k_prep(const float* __restrict__ w1,
                       const float* b1, const float* g1, const float* be1,
                       const float* m1, const float* v1,
                       const float* b2, const float* g2, const float* be2,
                       const float* m2, const float* v2) {
    int bx = blockIdx.x, tid = threadIdx.x;
    if (bx < 3072) {
        // W1 transpose (H,E,3) -> [k][e][h]
        int idx = bx * 256 + tid;
        int h = idx / (EDIM * 3);
        int r = idx % (EDIM * 3);
        int e = r / 3;
        int k = r % 3;
        g_W1t[(k * EDIM + e) * HDIM + h] = w1[idx];
    } else {
        int zb = bx - 3072;                 // 0..127
        int i = zb * 256 + tid;             // zero halo rows of y1t
        int b = i / (2 * HDIM);
        int rr = i % (2 * HDIM);
        int p = (rr < HDIM) ? 0 : (PPAD - 1);
        int h = rr % HDIM;
        g_y1t[((size_t)b * PPAD + p) * HDIM + h] = 0.f;
        if (zb == 0) {
#pragma unroll
            for (int q = 0; q < 2; ++q) {
                int hh = tid + q * 256;
                float s1 = g1[hh] * rsqrtf(v1[hh] + EPSV);
                g_c1[hh] = b1[hh] * s1 + be1[hh] - m1[hh] * s1;
                float s2 = g2[hh] * rsqrtf(v2[hh] + EPSV);
                g_c2[hh] = b2[hh] * s2 + be2[hh] - m2[hh] * s2;
            }
        }
    }
}

// ---------------- launch 1: Atab + W2k (fused) ----------------
__global__ void k_tab(const float* __restrict__ emb,
                      const float* __restrict__ g1, const float* __restrict__ v1,
                      const float* __restrict__ w2,
                      const float* __restrict__ g2, const float* __restrict__ v2) {
    __shared__ float es[EDIM];
    int bx = blockIdx.x, tid = threadIdx.x;   // 512 threads
    if (bx < 300) {
        // Atab[k][v][h] = scale1[h]*(emb[v] . W1[h,:,k])
        int v = bx / 3, k = bx % 3, h = tid;
        es[h] = emb[v * EDIM + h];
        __syncthreads();
        const float* w = g_W1t + (size_t)k * EDIM * HDIM + h;
        float acc = 0.f;
#pragma unroll 8
        for (int e = 0; e < EDIM; ++e)
            acc += es[e] * w[(size_t)e * HDIM];
        float scale = g1[h] * rsqrtf(v1[h] + EPSV);
        g_Atab[((size_t)k * VDIM + v) * HDIM + h] = acc * scale;
    } else {
        // W2k[tap][h][h'] = tf32(scale2[h]*W2[h,h',tap])
        int idx = (bx - 300) * 512 + tid;
        int tap = idx / (HDIM * HDIM);
        int r = idx % (HDIM * HDIM);
        int h = r / HDIM;
        int hp = r % HDIM;
        float s2 = g2[h] * rsqrtf(v2[h] + EPSV);
        float val = w2[h * HDIM * 3 + hp * 3 + tap] * s2;
        ((uint32_t*)g_W2k)[idx] = f2tf32(val);
    }
}

// ---------------- launch 2: y1 via table lookups -> transposed, padded, tf32 ----------------
__global__ void k_y1(const int* __restrict__ ids) {
    __shared__ int sid[18];
    int b = blockIdx.x;
    int p0 = blockIdx.y * 16;
    int tid = threadIdx.x;   // 256
    if (tid < 18) {
        int q = p0 - 1 + tid;
        sid[tid] = (q >= 0 && q < PDIM) ? ids[b * PDIM + q] : -1;
    }
    __syncthreads();
    uint32_t* out = (uint32_t*)g_y1t;
    for (int h = tid; h < HDIM; h += 256) {
        float cc = g_c1[h];
#pragma unroll
        for (int pl = 0; pl < 16; ++pl) {
            int i0 = sid[pl], i1 = sid[pl + 1], i2 = sid[pl + 2];
            float v = cc;
            if (i0 >= 0) v += g_Atab[(0 * VDIM + i0) * HDIM + h];
            if (i1 >= 0) v += g_Atab[(1 * VDIM + i1) * HDIM + h];
            if (i2 >= 0) v += g_Atab[(2 * VDIM + i2) * HDIM + h];
            v = fmaxf(v, 0.f);
            out[((size_t)b * PPAD + p0 + pl + 1) * HDIM + h] = f2tf32(v);
        }
    }
}

// ---------------- launch 3: conv2 GEMM, mma.sync tf32, shared-B across taps ----------------
__global__ __launch_bounds__(256, 1) void k_gemm() {
    extern __shared__ __align__(1024) char smem[];
    uint32_t sb = smem_u32(smem);
    int tid = threadIdx.x;
    int lane = tid & 31, wid = tid >> 5;
    int wm = wid & 1;          // 2 m-tiles of 64
    int wn = wid >> 1;         // 4 n-tiles of 64
    int p0 = blockIdx.x * TN;
    int h0 = blockIdx.y * TM;
    int b = blockIdx.z;

    // ---- per-lane ldmatrix address components ----
    uint32_t aBase[4], aXor[4];
#pragma unroll
    for (int fi = 0; fi < 4; ++fi) {
        int row = wm * 64 + fi * 16 + (lane & 15);
        aBase[fi] = row * 128;
        aXor[fi] = (row & 7) * 16;
    }
    uint32_t aK0 = (lane >> 4) * 16;

    int nb = (lane & 7) | ((lane & 16) >> 1);
    uint32_t bK0 = ((lane >> 3) & 1) * 16;
    int bRow[4];
#pragma unroll
    for (int half = 0; half < 4; ++half)
        bRow[half] = wn * 64 + half * 16 + nb;

    // ---- stage loader: 3 A tap tiles + shared B halo tile ----
    auto load_stage = [&](int c, int s) {
        int kk = c * TK;
        uint32_t st = sb + s * STAGE_BYTES;
#pragma unroll
        for (int j = 0; j < 21; ++j) {
            int i = tid + j * 256;
            if (i >= 5184) break;
            if (i < 3072) {                    // A: tap tiles, 128 rows x 128B each
                int tap = i >> 10;
                int r = i & 1023;
                int row = r >> 3, seg = r & 7;
                const float* g = g_W2k + ((size_t)tap * HDIM + h0 + row) * HDIM + kk + seg * 4;
                cp_async16(st + tap * A_TAP_BYTES + sw128((uint32_t)(row * 128 + seg * 16)), g);
            } else {                           // B: halo rows p0-1 .. p0+256 (+pad clamp)
                int ii = i - 3072;
                int row = ii >> 3, seg = ii & 7;
                int rowc = row < 258 ? row : 257;
                const float* g = g_y1t + ((size_t)b * PPAD + p0 + rowc) * HDIM + kk + seg * 4;
                cp_async16(st + A_BYTES + sw128((uint32_t)(row * 128 + seg * 16)), g);
            }
        }
    };

    float acc[4][8][4];
#pragma unroll
    for (int fi = 0; fi < 4; ++fi)
#pragma unroll
        for (int ni = 0; ni < 8; ++ni)
#pragma unroll
            for (int q = 0; q < 4; ++q) acc[fi][ni][q] = 0.f;

    load_stage(0, 0); CP_COMMIT();
    load_stage(1, 1); CP_COMMIT();

    for (int c = 0; c < NCHUNK; ++c) {
        CP_WAIT1();
        __syncthreads();
        uint32_t st = sb + (c & 1) * STAGE_BYTES;
        uint32_t stB = st + A_BYTES;
#pragma unroll
        for (int tap = 0; tap < 3; ++tap) {
            uint32_t stA = st + tap * A_TAP_BYTES;
#pragma unroll
            for (int j = 0; j < 4; ++j) {
                uint32_t a[4][4], bf[4][4];
#pragma unroll
                for (int fi = 0; fi < 4; ++fi) {
                    uint32_t addr = stA + aBase[fi] + ((aK0 + j * 32) ^ aXor[fi]);
                    LDSM_X4(a[fi][0], a[fi][1], a[fi][2], a[fi][3], addr);
                }
#pragma unroll
                for (int half = 0; half < 4; ++half) {
                    int row = bRow[half] + tap;
                    uint32_t addr = stB + row * 128 + ((bK0 + j * 32) ^ ((row & 7) * 16));
                    LDSM_X4(bf[half][0], bf[half][1], bf[half][2], bf[half][3], addr);
                }
#pragma unroll
                for (int fi = 0; fi < 4; ++fi)
#pragma unroll
                    for (int ni = 0; ni < 8; ++ni)
                        mma1688(acc[fi][ni], a[fi][0], a[fi][1], a[fi][2], a[fi][3],
                                bf[ni >> 1][(ni & 1) * 2], bf[ni >> 1][(ni & 1) * 2 + 1]);
            }
        }
        __syncthreads();
        if (c + 2 < NCHUNK) load_stage(c + 2, c & 1);
        CP_COMMIT();
    }

    // ---- epilogue: bias + relu, direct store to y2[b][h][p] ----
    int hr = h0 + wm * 64 + (lane >> 2);
    int pc = p0 + wn * 64 + (lane & 3) * 2;
#pragma unroll
    for (int fi = 0; fi < 4; ++fi) {
        int h = hr + fi * 16;
        float c0 = g_c2[h];
        float c1 = g_c2[h + 8];
        float* base0 = g_y2 + ((size_t)b * HDIM + h) * PDIM;
        float* base1 = base0 + 8 * PDIM;
#pragma unroll
        for (int ni = 0; ni < 8; ++ni) {
            int p = pc + ni * 8;
            float2 v0, v1;
            v0.x = fmaxf(acc[fi][ni][0] + c0, 0.f);
            v0.y = fmaxf(acc[fi][ni][1] + c0, 0.f);
            v1.x = fmaxf(acc[fi][ni][2] + c1, 0.f);
            v1.y = fmaxf(acc[fi][ni][3] + c1, 0.f);
            *(float2*)(base0 + p) = v0;
            *(float2*)(base1 + p) = v1;
        }
    }
}

// ---------------- launch 4: duration scan + frame->phoneme map ----------------
__global__ void k_scan(const int* __restrict__ durs, int F) {
    int b = blockIdx.x;
    int tid = threadIdx.x;   // 1024
    __shared__ int s[PDIM];
    int d = durs[b * PDIM + tid];
    s[tid] = d;
    __syncthreads();
    for (int off = 1; off < PDIM; off <<= 1) {
        int t = (tid >= off) ? s[tid - off] : 0;
        __syncthreads();
        s[tid] += t;
        __syncthreads();
    }
    int cum = s[tid];
    int total = s[PDIM - 1];
    int start = cum - d;
    for (int f = start; f < cum; ++f) g_fidx[b * MAXF + f] = tid;
    for (int f = total + tid; f < F; f += PDIM) g_fidx[b * MAXF + f] = -1;
}

// ---------------- launch 5: gather + mask ----------------
__global__ void k_gather(float* __restrict__ out, int F) {
    int bh = blockIdx.x;
    int b = bh / HDIM;
    const float* row = g_y2 + (size_t)bh * PDIM;
    const int* fx = g_fidx + b * MAXF;
    float* o = out + (size_t)bh * F;
    for (int f = threadIdx.x; f < F; f += blockDim.x) {
        int ix = fx[f];
        o[f] = (ix >= 0) ? row[ix] : 0.f;
    }
}

// ---------------- launch ----------------
extern "C" void kernel_launch(void* const* d_in, const int* in_sizes, int n_in,
                              void* d_out, int out_size) {
    const int* ids   = (const int*)d_in[0];
    const int* durs  = (const int*)d_in[1];
    const float* emb = (const float*)d_in[2];
    const float* w1  = (const float*)d_in[3];
    const float* b1  = (const float*)d_in[4];
    const float* g1  = (const float*)d_in[5];
    const float* be1 = (const float*)d_in[6];
    const float* m1  = (const float*)d_in[7];
    const float* v1  = (const float*)d_in[8];
    const float* w2  = (const float*)d_in[9];
    const float* b2  = (const float*)d_in[10];
    const float* g2  = (const float*)d_in[11];
    const float* be2 = (const float*)d_in[12];
    const float* m2  = (const float*)d_in[13];
    const float* v2  = (const float*)d_in[14];
    float* out = (float*)d_out;
    int F = out_size / (BDIM * HDIM);

    cudaFuncSetAttribute(k_gemm, cudaFuncAttributeMaxDynamicSharedMemorySize, GEMM_SMEM);

    k_prep<<<3200, 256>>>(w1, b1, g1, be1, m1, v1, b2, g2, be2, m2, v2);        // launch 0
    k_tab<<<300 + 1536, 512>>>(emb, g1, v1, w2, g2, v2);                        // launch 1
    k_y1<<<dim3(BDIM, PDIM / 16), 256>>>(ids);                                  // launch 2
    k_gemm<<<dim3(PDIM / TN, HDIM / TM, BDIM), 256, GEMM_SMEM>>>();             // launch 3 (profiled)
    k_scan<<<BDIM, PDIM>>>(durs, F);                                            // launch 4
    k_gather<<<BDIM * HDIM, 256>>>(out, F);                                     // launch 5
}

// round 7
// speedup vs baseline: 1.3237x; 1.3237x over previous
#include <cuda_runtime.h>
#include <cuda_fp16.h>
#include <cstdint>

#define BDIM 32
#define PDIM 1024
#define VDIM 100
#define EDIM 512
#define HDIM 512
#define EPSV 1e-5f
#define MAXF 9216
#define PPAD (PDIM + 2)

// GEMM tiling: CTA 128x256, fp16 mma.sync, shared-B across taps, 2-stage cp.async
#define TM 128
#define TN 256
#define TKH 64                             // K elems (fp16) per chunk = 128B rows
#define NCHUNK (HDIM / TKH)                // 8
#define A_TAP_BYTES (TM * 128)             // 16384 per tap
#define A_BYTES (3 * A_TAP_BYTES)          // 49152
#define B_ROWS_PAD 264                     // 256 + 2 halo, padded
#define B_BYTES (B_ROWS_PAD * 128)         // 33792
#define STAGE_BYTES (A_BYTES + B_BYTES)    // 82944
#define GEMM_SMEM (2 * STAGE_BYTES)        // 165888

// ---------------- scratch (static device globals) ----------------
__device__ float  g_W1t[3 * EDIM * HDIM];            // [k][e][h]
__device__ float  g_Atab[3 * VDIM * HDIM];           // [k][v][h]
__device__ float  g_c1[HDIM];
__device__ float  g_c2[HDIM];
__device__ __half g_W2k[3 * HDIM * HDIM];            // [tap][h][h'] fp16, K-major
__device__ __half g_y1t[(size_t)BDIM * PPAD * HDIM]; // [b][p+1][h'] fp16, halo rows zero
__device__ float  g_y2[(size_t)BDIM * HDIM * PDIM];  // [b][h][p]
__device__ int    g_fidx[BDIM * MAXF];

// ---------------- PTX helpers (base ISA only) ----------------
__device__ __forceinline__ uint32_t smem_u32(const void* p) {
    uint32_t a;
    asm("{ .reg .u64 t; cvta.to.shared.u64 t, %1; cvt.u32.u64 %0, t; }" : "=r"(a) : "l"(p));
    return a;
}
__device__ __forceinline__ void cp_async16(uint32_t s, const void* g) {
    asm volatile("cp.async.cg.shared.global [%0], [%1], 16;" :: "r"(s), "l"(g) : "memory");
}
#define CP_COMMIT() asm volatile("cp.async.commit_group;" ::: "memory")
#define CP_WAIT1()  asm volatile("cp.async.wait_group 1;" ::: "memory")

#define LDSM_X4(r0, r1, r2, r3, addr)                                        \
    asm volatile("ldmatrix.sync.aligned.m8n8.x4.shared.b16 {%0,%1,%2,%3}, [%4];" \
        : "=r"(r0), "=r"(r1), "=r"(r2), "=r"(r3) : "r"(addr))

__device__ __forceinline__ void mma16816(float* d, uint32_t a0, uint32_t a1,
                                         uint32_t a2, uint32_t a3,
                                         uint32_t b0, uint32_t b1) {
    asm volatile(
        "mma.sync.aligned.m16n8k16.row.col.f32.f16.f16.f32 "
        "{%0,%1,%2,%3}, {%4,%5,%6,%7}, {%8,%9}, {%0,%1,%2,%3};"
        : "+f"(d[0]), "+f"(d[1]), "+f"(d[2]), "+f"(d[3])
        : "r"(a0), "r"(a1), "r"(a2), "r"(a3), "r"(b0), "r"(b1));
}

__device__ __forceinline__ uint32_t sw128(uint32_t off) { return off ^ ((off >> 3) & 0x70); }

// ---------------- launch 0: fold-BN vectors + W1 transpose + y1t halo zero ----------------
__global__ void k_prep(const float* __restrict__ w1,
                       const float* b1, const float* g1, const float* be1,
                       const float* m1, const float* v1,
                       const float* b2, const float* g2, const float* be2,
                       const float* m2, const float* v2) {
    int bx = blockIdx.x, tid = threadIdx.x;
    if (bx < 3072) {
        // W1 transpose (H,E,3) -> [k][e][h]
        int idx = bx * 256 + tid;
        int h = idx / (EDIM * 3);
        int r = idx % (EDIM * 3);
        int e = r / 3;
        int k = r % 3;
        g_W1t[(k * EDIM + e) * HDIM + h] = w1[idx];
    } else {
        int zb = bx - 3072;                 // 0..63: zero halo rows of y1t (as uint32 words)
        int i = zb * 256 + tid;             // 16384 words = 32 b * 2 rows * 256 words
        int b = i / 512;
        int r = i % 512;
        int p = (r < 256) ? 0 : (PPAD - 1);
        int hw = r % 256;
        ((uint32_t*)g_y1t)[((size_t)b * PPAD + p) * (HDIM / 2) + hw] = 0u;
        if (zb == 0) {
#pragma unroll
            for (int q = 0; q < 2; ++q) {
                int hh = tid + q * 256;
                float s1 = g1[hh] * rsqrtf(v1[hh] + EPSV);
                g_c1[hh] = b1[hh] * s1 + be1[hh] - m1[hh] * s1;
                float s2 = g2[hh] * rsqrtf(v2[hh] + EPSV);
                g_c2[hh] = b2[hh] * s2 + be2[hh] - m2[hh] * s2;
            }
        }
    }
}

// ---------------- launch 1: Atab + W2k(fp16) fused ----------------
__global__ void k_tab(const float* __restrict__ emb,
                      const float* __restrict__ g1, const float* __restrict__ v1,
                      const float* __restrict__ w2,
                      const float* __restrict__ g2, const float* __restrict__ v2) {
    __shared__ float es[EDIM];
    int bx = blockIdx.x, tid = threadIdx.x;   // 512 threads
    if (bx < 300) {
        // Atab[k][v][h] = scale1[h]*(emb[v] . W1[h,:,k])
        int v = bx / 3, k = bx % 3, h = tid;
        es[h] = emb[v * EDIM + h];
        __syncthreads();
        const float* w = g_W1t + (size_t)k * EDIM * HDIM + h;
        float acc = 0.f;
#pragma unroll 8
        for (int e = 0; e < EDIM; ++e)
            acc += es[e] * w[(size_t)e * HDIM];
        float scale = g1[h] * rsqrtf(v1[h] + EPSV);
        g_Atab[((size_t)k * VDIM + v) * HDIM + h] = acc * scale;
    } else {
        // W2k[tap][h][hp] = fp16(scale2[h]*W2[h,hp,tap]), packed pairs
        int pidx = (bx - 300) * 512 + tid;       // over 3*512*256 half2 pairs
        int tap = pidx / (HDIM * (HDIM / 2));
        int r = pidx % (HDIM * (HDIM / 2));
        int h = r / (HDIM / 2);
        int hp = (r % (HDIM / 2)) * 2;
        float s2 = g2[h] * rsqrtf(v2[h] + EPSV);
        float v0 = w2[h * HDIM * 3 + hp * 3 + tap] * s2;
        float v1f = w2[h * HDIM * 3 + (hp + 1) * 3 + tap] * s2;
        ((half2*)g_W2k)[pidx] = __floats2half2_rn(v0, v1f);
    }
}

// ---------------- launch 2: y1 table lookups -> transposed, padded, fp16 ----------------
__global__ void k_y1(const int* __restrict__ ids) {
    __shared__ int sid[18];
    int b = blockIdx.x;
    int p0 = blockIdx.y * 16;
    int tid = threadIdx.x;   // 256
    if (tid < 18) {
        int q = p0 - 1 + tid;
        sid[tid] = (q >= 0 && q < PDIM) ? ids[b * PDIM + q] : -1;
    }
    __syncthreads();
    int h = tid * 2;                       // each thread: one half2 pair
    float c0 = g_c1[h], c1 = g_c1[h + 1];
    half2* out = (half2*)g_y1t;
#pragma unroll
    for (int pl = 0; pl < 16; ++pl) {
        int i0 = sid[pl], i1 = sid[pl + 1], i2 = sid[pl + 2];
        float v0 = c0, v1 = c1;
        if (i0 >= 0) {
            const float* a = g_Atab + (0 * VDIM + i0) * HDIM + h;
            v0 += a[0]; v1 += a[1];
        }
        if (i1 >= 0) {
            const float* a = g_Atab + (1 * VDIM + i1) * HDIM + h;
            v0 += a[0]; v1 += a[1];
        }
        if (i2 >= 0) {
            const float* a = g_Atab + (2 * VDIM + i2) * HDIM + h;
            v0 += a[0]; v1 += a[1];
        }
        v0 = fmaxf(v0, 0.f);
        v1 = fmaxf(v1, 0.f);
        out[((size_t)b * PPAD + p0 + pl + 1) * (HDIM / 2) + tid] = __floats2half2_rn(v0, v1);
    }
}

// ---------------- launch 3: conv2 GEMM, mma.sync fp16, shared-B across taps ----------------
__global__ __launch_bounds__(512, 1) void k_gemm() {
    extern __shared__ __align__(1024) char smem[];
    uint32_t sb = smem_u32(smem);
    int tid = threadIdx.x;
    int lane = tid & 31, wid = tid >> 5;   // 16 warps
    int wm = wid & 3;          // 4 m-tiles of 32
    int wn = wid >> 2;         // 4 n-tiles of 64
    int p0 = blockIdx.x * TN;
    int h0 = blockIdx.y * TM;
    int b = blockIdx.z;

    // ---- per-lane ldmatrix address components (128B K-major rows, SW128) ----
    uint32_t aBase[2], aXor[2];
#pragma unroll
    for (int fi = 0; fi < 2; ++fi) {
        int row = wm * 32 + fi * 16 + (lane & 15);
        aBase[fi] = row * 128;
        aXor[fi] = (row & 7) * 16;
    }
    uint32_t aK0 = (lane >> 4) * 16;

    int nb = (lane & 7) | ((lane & 16) >> 1);
    uint32_t bK0 = ((lane >> 3) & 1) * 16;
    int bRow[4];
#pragma unroll
    for (int half = 0; half < 4; ++half)
        bRow[half] = wn * 64 + half * 16 + nb;

    // ---- stage loader: 3 A tap tiles + shared B halo tile (fp16) ----
    auto load_stage = [&](int c, int s) {
        int kk = c * TKH;
        uint32_t st = sb + s * STAGE_BYTES;
#pragma unroll
        for (int j = 0; j < 11; ++j) {
            int i = tid + j * 512;
            if (i >= 5184) break;
            if (i < 3072) {                    // A: 3 tap tiles, 128 rows x 128B
                int tap = i >> 10;
                int r = i & 1023;
                int row = r >> 3, seg = r & 7;
                const __half* g = g_W2k + ((size_t)tap * HDIM + h0 + row) * HDIM + kk + seg * 8;
                cp_async16(st + tap * A_TAP_BYTES + sw128((uint32_t)(row * 128 + seg * 16)), g);
            } else {                           // B: halo rows p0-1 .. p0+256 (+pad clamp)
                int ii = i - 3072;
                int row = ii >> 3, seg = ii & 7;
                int rowc = row < 258 ? row : 257;
                const __half* g = g_y1t + ((size_t)b * PPAD + p0 + rowc) * HDIM + kk + seg * 8;
                cp_async16(st + A_BYTES + sw128((uint32_t)(row * 128 + seg * 16)), g);
            }
        }
    };

    float acc[2][8][4];
#pragma unroll
    for (int fi = 0; fi < 2; ++fi)
#pragma unroll
        for (int ni = 0; ni < 8; ++ni)
#pragma unroll
            for (int q = 0; q < 4; ++q) acc[fi][ni][q] = 0.f;

    load_stage(0, 0); CP_COMMIT();
    load_stage(1, 1); CP_COMMIT();

    for (int c = 0; c < NCHUNK; ++c) {
        CP_WAIT1();
        __syncthreads();
        uint32_t st = sb + (c & 1) * STAGE_BYTES;
        uint32_t stB = st + A_BYTES;
#pragma unroll
        for (int tap = 0; tap < 3; ++tap) {
            uint32_t stA = st + tap * A_TAP_BYTES;
#pragma unroll
            for (int j = 0; j < 4; ++j) {      // 4 k16 steps per 128B row
                uint32_t a[2][4], bf[4][4];
#pragma unroll
                for (int fi = 0; fi < 2; ++fi) {
                    uint32_t addr = stA + aBase[fi] + ((aK0 + j * 32) ^ aXor[fi]);
                    LDSM_X4(a[fi][0], a[fi][1], a[fi][2], a[fi][3], addr);
                }
#pragma unroll
                for (int half = 0; half < 4; ++half) {
                    int row = bRow[half] + tap;
                    uint32_t addr = stB + row * 128 + ((bK0 + j * 32) ^ ((row & 7) * 16));
                    LDSM_X4(bf[half][0], bf[half][1], bf[half][2], bf[half][3], addr);
                }
#pragma unroll
                for (int fi = 0; fi < 2; ++fi)
#pragma unroll
                    for (int ni = 0; ni < 8; ++ni)
                        mma16816(acc[fi][ni], a[fi][0], a[fi][1], a[fi][2], a[fi][3],
                                 bf[ni >> 1][(ni & 1) * 2], bf[ni >> 1][(ni & 1) * 2 + 1]);
            }
        }
        __syncthreads();
        if (c + 2 < NCHUNK) load_stage(c + 2, c & 1);
        CP_COMMIT();
    }

    // ---- epilogue: bias + relu, direct store to y2[b][h][p] ----
    int hr = h0 + wm * 32 + (lane >> 2);
    int pc = p0 + wn * 64 + (lane & 3) * 2;
#pragma unroll
    for (int fi = 0; fi < 2; ++fi) {
        int h = hr + fi * 16;
        float c0 = g_c2[h];
        float c1 = g_c2[h + 8];
        float* base0 = g_y2 + ((size_t)b * HDIM + h) * PDIM;
        float* base1 = base0 + 8 * PDIM;
#pragma unroll
        for (int ni = 0; ni < 8; ++ni) {
            int p = pc + ni * 8;
            float2 v0, v1;
            v0.x = fmaxf(acc[fi][ni][0] + c0, 0.f);
            v0.y = fmaxf(acc[fi][ni][1] + c0, 0.f);
            v1.x = fmaxf(acc[fi][ni][2] + c1, 0.f);
            v1.y = fmaxf(acc[fi][ni][3] + c1, 0.f);
            *(float2*)(base0 + p) = v0;
            *(float2*)(base1 + p) = v1;
        }
    }
}

// ---------------- launch 4: duration scan + frame->phoneme map ----------------
__global__ void k_scan(const int* __restrict__ durs, int F) {
    int b = blockIdx.x;
    int tid = threadIdx.x;   // 1024
    __shared__ int s[PDIM];
    int d = durs[b * PDIM + tid];
    s[tid] = d;
    __syncthreads();
    for (int off = 1; off < PDIM; off <<= 1) {
        int t = (tid >= off) ? s[tid - off] : 0;
        __syncthreads();
        s[tid] += t;
        __syncthreads();
    }
    int cum = s[tid];
    int total = s[PDIM - 1];
    int start = cum - d;
    for (int f = start; f < cum; ++f) g_fidx[b * MAXF + f] = tid;
    for (int f = total + tid; f < F; f += PDIM) g_fidx[b * MAXF + f] = -1;
}

// ---------------- launch 5: gather + mask ----------------
__global__ void k_gather(float* __restrict__ out, int F) {
    int bh = blockIdx.x;
    int b = bh / HDIM;
    const float* row = g_y2 + (size_t)bh * PDIM;
    const int* fx = g_fidx + b * MAXF;
    float* o = out + (size_t)bh * F;
    for (int f = threadIdx.x; f < F; f += blockDim.x) {
        int ix = fx[f];
        o[f] = (ix >= 0) ? row[ix] : 0.f;
    }
}

// ---------------- launch ----------------
extern "C" void kernel_launch(void* const* d_in, const int* in_sizes, int n_in,
                              void* d_out, int out_size) {
    const int* ids   = (const int*)d_in[0];
    const int* durs  = (const int*)d_in[1];
    const float* emb = (const float*)d_in[2];
    const float* w1  = (const float*)d_in[3];
    const float* b1  = (const float*)d_in[4];
    const float* g1  = (const float*)d_in[5];
    const float* be1 = (const float*)d_in[6];
    const float* m1  = (const float*)d_in[7];
    const float* v1  = (const float*)d_in[8];
    const float* w2  = (const float*)d_in[9];
    const float* b2  = (const float*)d_in[10];
    const float* g2  = (const float*)d_in[11];
    const float* be2 = (const float*)d_in[12];
    const float* m2  = (const float*)d_in[13];
    const float* v2  = (const float*)d_in[14];
    float* out = (float*)d_out;
    int F = out_size / (BDIM * HDIM);

    cudaFuncSetAttribute(k_gemm, cudaFuncAttributeMaxDynamicSharedMemorySize, GEMM_SMEM);

    k_prep<<<3072 + 64, 256>>>(w1, b1, g1, be1, m1, v1, b2, g2, be2, m2, v2);   // launch 0
    k_tab<<<300 + 768, 512>>>(emb, g1, v1, w2, g2, v2);                         // launch 1
    k_y1<<<dim3(BDIM, PDIM / 16), 256>>>(ids);                                  // launch 2
    k_gemm<<<dim3(PDIM / TN, HDIM / TM, BDIM), 512, GEMM_SMEM>>>();             // launch 3 (profiled)
    k_scan<<<BDIM, PDIM>>>(durs, F);                                            // launch 4
    k_gather<<<BDIM * HDIM, 256>>>(out, F);                                     // launch 5
}